// round 7
// baseline (speedup 1.0000x reference)
#include <cuda_runtime.h>
#include <cuda_fp16.h>

// DifferentiableCensus: out = (1/9) * sum_{3x3, edge-clamped} sigmoid(neighbor - center)
// x: (16,3,512,512) f32 -> 48 independent 512x512 images.
//
// Round 7: L1tex-wavefront bound -> halo values via warp shuffle.
//  - 1 thread = 4 cols x 4 rows; 6 rows front-batched as LDG.128 (MLP=6).
//  - Column halos come from neighbor lanes' registers (SHFL), with
//    predicated 1-line LDGs only at warp boundaries. Load wavefronts/thread
//    drop 72 -> ~26.
//  - half2 SIMD datapath: tanh.approx.f16x2, every pixel-pair edge computed
//    once (reverse term = negation), PRMT lane realignment.

static constexpr int H = 512;
static constexpr int W = 512;
static constexpr int ROWS_PER_THREAD = 4;
static constexpr int BLOCK_X = 128;            // 128 threads * 4 cols = 512 cols

__device__ __forceinline__ __half2 tanh_h2(__half2 h) {
    unsigned u = *reinterpret_cast<unsigned*>(&h);
    unsigned r;
    asm("tanh.approx.f16x2 %0, %1;" : "=r"(r) : "r"(u));
    return *reinterpret_cast<__half2*>(&r);
}

__device__ __forceinline__ __half2 prmt(__half2 a, __half2 b, unsigned sel) {
    unsigned r = __byte_perm(*reinterpret_cast<unsigned*>(&a),
                             *reinterpret_cast<unsigned*>(&b), sel);
    return *reinterpret_cast<__half2*>(&r);
}
// sel: (a.lo,b.lo)=0x5410  (a.hi,b.lo)=0x5432  swap(a)=0x1032

struct Row { __half2 m1, m2, lr; };   // m1=(v1,v2) m2=(v3,v4) lr=(v0,v5); v0/v5 clamped halos

__global__ __launch_bounds__(BLOCK_X)
void census_kernel(const float* __restrict__ x, float* __restrict__ out) {
    const int c0   = threadIdx.x * 4;
    const int lane = threadIdx.x & 31;
    const int r0   = blockIdx.y * ROWS_PER_THREAD;
    const int img  = blockIdx.z;

    const float* __restrict__ xi = x   + (size_t)img * H * W;
    float* __restrict__       oi = out + (size_t)img * H * W;

    // ---- Front-batched main loads: 6 rows of LDG.128, all independent ----
    const float* rowp[6];
    float4 m4[6];
    #pragma unroll
    for (int j = 0; j < 6; j++) {
        const int g = min(max(r0 - 1 + j, 0), H - 1);
        rowp[j] = xi + (size_t)g * W;
        m4[j] = __ldg(reinterpret_cast<const float4*>(rowp[j] + c0));
    }

    // ---- Halos from neighbor lanes (no scattered LDGs) ----
    float lf[6], rf[6];
    #pragma unroll
    for (int j = 0; j < 6; j++) {
        lf[j] = __shfl_up_sync(0xffffffffu, m4[j].w, 1);    // col c0-1
        rf[j] = __shfl_down_sync(0xffffffffu, m4[j].x, 1);  // col c0+4
    }
    if (lane == 0) {
        const bool edge = (c0 == 0);
        #pragma unroll
        for (int j = 0; j < 6; j++)
            lf[j] = edge ? m4[j].x : __ldg(rowp[j] + c0 - 1);   // 1-line LDG
    }
    if (lane == 31) {
        const bool edge = (c0 + 4 >= W);
        #pragma unroll
        for (int j = 0; j < 6; j++)
            rf[j] = edge ? m4[j].w : __ldg(rowp[j] + c0 + 4);   // 1-line LDG
    }

    // ---- Pack prescaled (x/2) rows into half2 ----
    Row rw[6];
    #pragma unroll
    for (int j = 0; j < 6; j++) {
        rw[j].m1 = __floats2half2_rn(0.5f * m4[j].x, 0.5f * m4[j].y);
        rw[j].m2 = __floats2half2_rn(0.5f * m4[j].z, 0.5f * m4[j].w);
        rw[j].lr = __floats2half2_rn(0.5f * lf[j],   0.5f * rf[j]);
    }

    // ---- Priming carries: S/SE/SW edge tanh between rows 0 (p) and 1 (b) ----
    __half2 pSa, pSb, pDRa, pDRb, pDLa, pDLb;
    {
        const Row& p = rw[0];
        const Row& b = rw[1];
        const __half2 bB = prmt(b.m1, b.m2, 0x5432);
        const __half2 bC = __halves2half2(__high2half(b.m2), __high2half(b.lr));
        const __half2 bA = __halves2half2(__low2half(b.lr), __low2half(b.m1));
        pSa  = tanh_h2(__hsub2(b.m1, p.m1)); pSb  = tanh_h2(__hsub2(b.m2, p.m2));
        pDRa = tanh_h2(__hsub2(bB,   p.m1)); pDRb = tanh_h2(__hsub2(bC,   p.m2));
        pDLa = tanh_h2(__hsub2(bA,   p.m1)); pDLb = tanh_h2(__hsub2(bB,   p.m2));
    }

    const __half2 zero = __float2half2_rn(0.0f);

    #pragma unroll
    for (int k = 0; k < ROWS_PER_THREAD; k++) {
        const Row& p = rw[k];
        const Row& b = rw[k + 1];
        const Row& n = rw[k + 2];

        const __half2 nB = prmt(n.m1, n.m2, 0x5432);
        const __half2 nA = __halves2half2(__low2half(n.lr), __low2half(n.m1));
        const __half2 nC = __halves2half2(__high2half(n.m2), __high2half(n.lr));
        const __half2 bB = prmt(b.m1, b.m2, 0x5432);
        const __half2 bC = __halves2half2(__high2half(b.m2), __high2half(b.lr));

        // Forward edges (2 tanh per MUFU issue); centers = b.m1/b.m2.
        const __half2 Sa  = tanh_h2(__hsub2(n.m1, b.m1)), Sb  = tanh_h2(__hsub2(n.m2, b.m2));
        const __half2 DRa = tanh_h2(__hsub2(nB,   b.m1)), DRb = tanh_h2(__hsub2(nC,   b.m2));
        const __half2 DLa = tanh_h2(__hsub2(nA,   b.m1)), DLb = tanh_h2(__hsub2(nB,   b.m2));
        const __half2 Ea  = tanh_h2(__hsub2(bB,   b.m1)), Eb  = tanh_h2(__hsub2(bC,   b.m2));

        // Halo edges: H1 = (W0, UL0), H2 = (UR3, UR3).
        const __half2 H1 = tanh_h2(__hsub2(
            __halves2half2(__low2half(b.lr), __low2half(p.lr)),   // (b0, p0)
            __half2half2(__low2half(b.m1))));                     // (b1, b1)
        const __half2 H2 = tanh_h2(__hsub2(
            __half2half2(__high2half(p.lr)),                      // (p5, p5)
            __half2half2(__high2half(b.m2))));                    // (b4, b4)

        // Aligned part: S + DR + DL - pS + E.
        __half2 al1 = __hadd2(__hadd2(Sa, DRa), __hsub2(DLa, pSa));
        __half2 al2 = __hadd2(__hadd2(Sb, DRb), __hsub2(DLb, pSb));
        al1 = __hadd2(al1, Ea);
        al2 = __hadd2(al2, Eb);

        // Misaligned part (PRMT lane realignment):
        //  (W0+UL0 - pDL1, -E0 - pDR0 - pDL2, -E1 - pDR1 - pDL3, -E2 - pDR2 + UR3)
        const __half2 sWU = __hadd2(H1, prmt(H1, H1, 0x1032));
        const __half2 nEa = __hneg2(Ea);
        const __half2 nEb = __hneg2(Eb);
        const __half2 nUR = __hneg2(H2);
        const __half2 Alo = prmt(sWU, nEa, 0x5410);               // (W0+UL0, -E0)
        const __half2 Ahi = prmt(nEa, nEb, 0x5432);               // (-E1, -E2)
        const __half2 Blo = prmt(zero, pDRa, 0x5410);             // (0, pDR0)
        const __half2 Bhi = prmt(pDRa, pDRb, 0x5432);             // (pDR1, pDR2)
        const __half2 Clo = prmt(pDLa, pDLb, 0x5432);             // (pDL1, pDL2)
        const __half2 Chi = prmt(pDLb, nUR, 0x5432);              // (pDL3, -UR3)

        const __half2 Tlo = __hadd2(al1, __hsub2(__hsub2(Alo, Blo), Clo));
        const __half2 Thi = __hadd2(al2, __hsub2(__hsub2(Ahi, Bhi), Chi));

        const float2 lo = __half22float2(Tlo);
        const float2 hi = __half22float2(Thi);
        float4 o;
        o.x = fmaf(lo.x, 1.0f / 18.0f, 0.5f);
        o.y = fmaf(lo.y, 1.0f / 18.0f, 0.5f);
        o.z = fmaf(hi.x, 1.0f / 18.0f, 0.5f);
        o.w = fmaf(hi.y, 1.0f / 18.0f, 0.5f);
        *reinterpret_cast<float4*>(oi + (size_t)(r0 + k) * W + c0) = o;

        // Carry forward edges as next row's reverse terms.
        pSa = Sa; pSb = Sb; pDRa = DRa; pDRb = DRb; pDLa = DLa; pDLb = DLb;
    }
}

extern "C" void kernel_launch(void* const* d_in, const int* in_sizes, int n_in,
                              void* d_out, int out_size) {
    (void)in_sizes; (void)n_in; (void)out_size;
    const float* x = (const float*)d_in[0];
    float* out = (float*)d_out;

    dim3 block(BLOCK_X, 1, 1);
    dim3 grid(1, H / ROWS_PER_THREAD, 16 * 3);
    census_kernel<<<grid, block>>>(x, out);
}

// round 8
// speedup vs baseline: 1.0239x; 1.0239x over previous
#include <cuda_runtime.h>

// DifferentiableCensus: out = (1/9) * sum_{3x3, edge-clamped} sigmoid(neighbor - center)
// x: (16,3,512,512) f32 -> 48 independent 512x512 images.
//
// Round 8: minimize real SASS instruction count.
//  Issued-slot analysis across R1-R7 shows dur = instr/issue%; the f32
//  edge-sharing kernel (R2) had the fewest instructions, capped by MUFU
//  pressure of exp+rcp sigmoid. This round: same minimal f32 datapath with
//  tanh.approx.f32 (1 MUFU, FSUB+MUFU+FADD per sigmoid, no packing).
//  sigmoid(d) = 0.5 + 0.5*tanh(d/2); accumulate signed tanh T; out = 0.5 + T/18.
//  4 cols x 8 rows per thread; each pixel-pair edge computed once, reverse
//  term = negation. Only the halo lanes of the previous row are carried.

static constexpr int H = 512;
static constexpr int W = 512;
static constexpr int ROWS_PER_THREAD = 8;
static constexpr int BLOCK_X = 128;            // 128 threads * 4 cols = 512 cols

__device__ __forceinline__ float tanh_ap(float v) {
    float r;
    asm("tanh.approx.f32 %0, %1;" : "=f"(r) : "f"(v));
    return r;
}

__device__ __forceinline__ void load_row(const float* __restrict__ row,
                                         int c0, int cl, int cr, float v[6]) {
    // v[0] = col c0-1 (clamped), v[1..4] = c0..c0+3, v[5] = c0+4 (clamped); all prescaled 0.5
    const float4 m = __ldg(reinterpret_cast<const float4*>(row + c0));
    v[0] = 0.5f * __ldg(row + cl);
    v[1] = 0.5f * m.x;
    v[2] = 0.5f * m.y;
    v[3] = 0.5f * m.z;
    v[4] = 0.5f * m.w;
    v[5] = 0.5f * __ldg(row + cr);
}

__global__ __launch_bounds__(BLOCK_X)
void census_kernel(const float* __restrict__ x, float* __restrict__ out) {
    const int c0  = threadIdx.x * 4;
    const int r0  = blockIdx.y * ROWS_PER_THREAD;
    const int img = blockIdx.z;

    const float* __restrict__ xi = x   + (size_t)img * H * W;
    float* __restrict__       oi = out + (size_t)img * H * W;

    const int cl = max(c0 - 1, 0);
    const int cr = min(c0 + 4, W - 1);

    float b[6];
    load_row(xi + (size_t)r0 * W, c0, cl, cr, b);

    // Priming carries from row r0-1 (p): S/SE/SW edge tanh, plus p's halo lanes.
    float pS[4], pDR[4], pDL[4], pl, pr;
    {
        float p[6];
        load_row(xi + (size_t)max(r0 - 1, 0) * W, c0, cl, cr, p);
        #pragma unroll
        for (int i = 0; i < 4; i++) {
            pS[i]  = tanh_ap(b[i + 1] - p[i + 1]);
            pDR[i] = tanh_ap(b[i + 2] - p[i + 1]);
            pDL[i] = tanh_ap(b[i]     - p[i + 1]);
        }
        pl = p[0]; pr = p[5];
    }

    #pragma unroll
    for (int k = 0; k < ROWS_PER_THREAD; k++) {
        const int r = r0 + k;
        float n[6];
        load_row(xi + (size_t)min(r + 1, H - 1) * W, c0, cl, cr, n);

        float tS[4], tDR[4], tDL[4], tE[4];
        #pragma unroll
        for (int i = 0; i < 4; i++) {
            tS[i]  = tanh_ap(n[i + 1] - b[i + 1]); // S
            tDR[i] = tanh_ap(n[i + 2] - b[i + 1]); // SE
            tDL[i] = tanh_ap(n[i]     - b[i + 1]); // SW
            tE[i]  = tanh_ap(b[i + 2] - b[i + 1]); // E
        }
        const float tW0  = tanh_ap(b[0] - b[1]);   // W  halo (col c0)
        const float tUL0 = tanh_ap(pl   - b[1]);   // NW halo (col c0)
        const float tUR3 = tanh_ap(pr   - b[4]);   // NE halo (col c0+3)

        // Signed sums: forward edges +, reverse of previously-computed edges -.
        const float T0 = (tS[0] + tDR[0]) + (tDL[0] - pS[0])
                       + (tE[0] + tW0)    + (tUL0   - pDL[1]);
        const float T1 = (tS[1] + tDR[1]) + (tDL[1] - pS[1])
                       + (tE[1] - tE[0])  - (pDR[0] + pDL[2]);
        const float T2 = (tS[2] + tDR[2]) + (tDL[2] - pS[2])
                       + (tE[2] - tE[1])  - (pDR[1] + pDL[3]);
        const float T3 = (tS[3] + tDR[3]) + (tDL[3] - pS[3])
                       + (tE[3] - tE[2])  + (tUR3   - pDR[2]);

        float4 o;
        o.x = fmaf(T0, 1.0f / 18.0f, 0.5f);
        o.y = fmaf(T1, 1.0f / 18.0f, 0.5f);
        o.z = fmaf(T2, 1.0f / 18.0f, 0.5f);
        o.w = fmaf(T3, 1.0f / 18.0f, 0.5f);
        *reinterpret_cast<float4*>(oi + (size_t)r * W + c0) = o;

        // Roll: keep only halo lanes of the old center row; carry forward edges.
        pl = b[0]; pr = b[5];
        #pragma unroll
        for (int i = 0; i < 6; i++) b[i] = n[i];
        #pragma unroll
        for (int i = 0; i < 4; i++) { pS[i] = tS[i]; pDR[i] = tDR[i]; pDL[i] = tDL[i]; }
    }
}

extern "C" void kernel_launch(void* const* d_in, const int* in_sizes, int n_in,
                              void* d_out, int out_size) {
    (void)in_sizes; (void)n_in; (void)out_size;
    const float* x = (const float*)d_in[0];
    float* out = (float*)d_out;

    dim3 block(BLOCK_X, 1, 1);
    dim3 grid(1, H / ROWS_PER_THREAD, 16 * 3);
    census_kernel<<<grid, block>>>(x, out);
}